// round 2
// baseline (speedup 1.0000x reference)
#include <cuda_runtime.h>

// Problem constants
#define D   32
#define MM  64
#define DD  1024          // D*D
#define F_OUT 2080        // M*(M+1)/2
#define FP  2112          // padded to 33*64
#define NB  16            // batch
#define BK  16            // GEMM k-tile

// ---------------- scratch (static device globals; no runtime allocation) ----
__device__ float g_A_re[(size_t)FP * DD];
__device__ float g_A_im[(size_t)FP * DD];
__device__ float g_H_re[(size_t)NB * DD * DD];
__device__ float g_H_im[(size_t)NB * DD * DD];
__device__ float g_T_re[(size_t)NB * FP * DD];
__device__ float g_T_im[(size_t)NB * FP * DD];

// ---------------- kernel 1: build 2-photon SLOS amplitudes -------------------
// A[f, x*32+y] = scale * (U[j,x]U[k,32+y] + U[k,x]U[j,32+y]),  (j,k)=triu pair f
__global__ void build_amps(const float* __restrict__ U_re,
                           const float* __restrict__ U_im) {
    int f = blockIdx.x;
    int t = threadIdx.x;
    if (f >= F_OUT) {                       // zero padding rows
        for (int i = t; i < DD; i += blockDim.x) {
            g_A_re[(size_t)f * DD + i] = 0.f;
            g_A_im[(size_t)f * DD + i] = 0.f;
        }
        return;
    }
    // invert f -> (j, k), j<=k, row-major upper-triangle enumeration
    int j = 0, rem = f;
    while (rem >= MM - j) { rem -= MM - j; ++j; }
    int k = j + rem;

    __shared__ float su[4][MM];             // U row j (re,im), U row k (re,im)
    if (t < MM) {
        su[0][t] = U_re[j * MM + t];
        su[1][t] = U_im[j * MM + t];
        su[2][t] = U_re[k * MM + t];
        su[3][t] = U_im[k * MM + t];
    }
    __syncthreads();

    float sc = (j == k) ? 0.7071067811865476f : 1.0f;
    for (int i = t; i < DD; i += blockDim.x) {
        int x = i >> 5, y = i & 31;
        float ar = su[0][x],     ai = su[1][x];        // U[j,x]
        float br = su[2][D + y], bi = su[3][D + y];    // U[k,D+y]
        float cr = su[2][x],     ci = su[3][x];        // U[k,x]
        float dr = su[0][D + y], di = su[1][D + y];    // U[j,D+y]
        float re = ar * br - ai * bi + cr * dr - ci * di;
        float im = ar * bi + ai * br + cr * di + ci * dr;
        g_A_re[(size_t)f * DD + i] = sc * re;
        g_A_im[(size_t)f * DD + i] = sc * im;
    }
}

// ---------------- kernel 2: Hermitianize rho from its upper triangle ---------
// H[i][j] = rho[i][j] (i<j);  conj(rho[j][i]) (i>j);  (Re(rho_ii), 0) (i==j)
__global__ void hermitize(const float* __restrict__ rho_re,
                          const float* __restrict__ rho_im) {
    int ti = blockIdx.x, tj = blockIdx.y, b = blockIdx.z;
    if (tj < ti) return;
    __shared__ float sr[32][33];
    __shared__ float si[32][33];
    int cx = threadIdx.x, ry = threadIdx.y;
    const size_t base = (size_t)b * DD * DD;
    int r = ti * 32 + ry, c = tj * 32 + cx;
    sr[ry][cx] = rho_re[base + (size_t)r * DD + c];
    si[ry][cx] = rho_im[base + (size_t)r * DD + c];
    __syncthreads();
    if (ti == tj) {
        float re, im;
        if (ry < cx)      { re = sr[ry][cx]; im = si[ry][cx]; }
        else if (ry > cx) { re = sr[cx][ry]; im = -si[cx][ry]; }
        else              { re = sr[ry][cx]; im = 0.f; }
        g_H_re[base + (size_t)r * DD + c] = re;
        g_H_im[base + (size_t)r * DD + c] = im;
    } else {
        g_H_re[base + (size_t)r * DD + c] = sr[ry][cx];
        g_H_im[base + (size_t)r * DD + c] = si[ry][cx];
        int r2 = tj * 32 + ry, c2 = ti * 32 + cx;       // mirrored tile
        g_H_re[base + (size_t)r2 * DD + c2] = sr[cx][ry];
        g_H_im[base + (size_t)r2 * DD + c2] = -si[cx][ry];
    }
}

// ---------------- shared 3M (Karatsuba) complex MMA inner tile ---------------
// planes: 0 = re, 1 = im, 2 = re+im  (B side carries conjugation pre-folded)
// acc0 += a_re*b_re, acc1 += a_im*b_im, acc2 += (a_re+a_im)*(b_re+b_im)
// out_re = acc0 - acc1,  out_im = acc2 - acc0 - acc1
__device__ __forceinline__ void mma_tile(float (*sA)[BK][64], float (*sB)[BK][64],
                                         int ty, int tx,
                                         float (&acc0)[4][4], float (&acc1)[4][4],
                                         float (&acc2)[4][4]) {
#pragma unroll
    for (int kk = 0; kk < BK; ++kk) {
        float4 a0 = *(const float4*)&sA[0][kk][ty * 4];
        float4 a1 = *(const float4*)&sA[1][kk][ty * 4];
        float4 a2 = *(const float4*)&sA[2][kk][ty * 4];
        float4 b0 = *(const float4*)&sB[0][kk][tx * 4];
        float4 b1 = *(const float4*)&sB[1][kk][tx * 4];
        float4 b2 = *(const float4*)&sB[2][kk][tx * 4];
        float A0[4] = {a0.x, a0.y, a0.z, a0.w};
        float A1[4] = {a1.x, a1.y, a1.z, a1.w};
        float A2[4] = {a2.x, a2.y, a2.z, a2.w};
        float B0[4] = {b0.x, b0.y, b0.z, b0.w};
        float B1[4] = {b1.x, b1.y, b1.z, b1.w};
        float B2[4] = {b2.x, b2.y, b2.z, b2.w};
#pragma unroll
        for (int i = 0; i < 4; ++i)
#pragma unroll
            for (int jx = 0; jx < 4; ++jx) {
                acc0[i][jx] += A0[i] * B0[jx];
                acc1[i][jx] += A1[i] * B1[jx];
                acc2[i][jx] += A2[i] * B2[jx];
            }
    }
}

// ---------------- kernel 3: T[b] = A @ H[b]  (complex, 3M) -------------------
__global__ __launch_bounds__(256) void gemm_stage1() {
    int bn = blockIdx.x;   // H column tile (0..15)
    int bm = blockIdx.y;   // A row tile    (0..32)
    int b  = blockIdx.z;
    __shared__ __align__(16) float sA[3][BK][64];
    __shared__ __align__(16) float sB[3][BK][64];
    int tid = threadIdx.x;
    const size_t hbase = (size_t)b * DD * DD;
    const float* __restrict__ Hre = g_H_re + hbase;
    const float* __restrict__ Him = g_H_im + hbase;

    float acc0[4][4] = {}, acc1[4][4] = {}, acc2[4][4] = {};

    const int am = tid >> 2;               // A row within tile (0..63)
    const int ak = (tid & 3) << 2;         // A k-offset (0,4,8,12)
    const size_t aoff = (size_t)(bm * 64 + am) * DD + ak;
    const int hn = tid & 63;               // H col within tile
    const int hk = tid >> 6;               // 0..3
    const int tx = tid & 15, ty = tid >> 4;

    for (int k0 = 0; k0 < DD; k0 += BK) {
        // A tile: row-major global -> [k][m] smem (transpose on store)
        float4 vr = *(const float4*)(g_A_re + aoff + k0);
        float4 vi = *(const float4*)(g_A_im + aoff + k0);
        sA[0][ak + 0][am] = vr.x; sA[1][ak + 0][am] = vi.x; sA[2][ak + 0][am] = vr.x + vi.x;
        sA[0][ak + 1][am] = vr.y; sA[1][ak + 1][am] = vi.y; sA[2][ak + 1][am] = vr.y + vi.y;
        sA[0][ak + 2][am] = vr.z; sA[1][ak + 2][am] = vi.z; sA[2][ak + 2][am] = vr.z + vi.z;
        sA[0][ak + 3][am] = vr.w; sA[1][ak + 3][am] = vi.w; sA[2][ak + 3][am] = vr.w + vi.w;
        // H tile: already [k][n]
#pragma unroll
        for (int s = 0; s < 4; ++s) {
            int kk = hk * 4 + s;
            float hr = Hre[(size_t)(k0 + kk) * DD + bn * 64 + hn];
            float hi = Him[(size_t)(k0 + kk) * DD + bn * 64 + hn];
            sB[0][kk][hn] = hr; sB[1][kk][hn] = hi; sB[2][kk][hn] = hr + hi;
        }
        __syncthreads();
        mma_tile(sA, sB, ty, tx, acc0, acc1, acc2);
        __syncthreads();
    }

    const size_t tbase = (size_t)b * FP * DD;
    int f0 = bm * 64 + ty * 4, n0 = bn * 64 + tx * 4;
#pragma unroll
    for (int i = 0; i < 4; ++i) {
        float4 wre = make_float4(acc0[i][0] - acc1[i][0], acc0[i][1] - acc1[i][1],
                                 acc0[i][2] - acc1[i][2], acc0[i][3] - acc1[i][3]);
        float4 wim = make_float4(acc2[i][0] - acc0[i][0] - acc1[i][0],
                                 acc2[i][1] - acc0[i][1] - acc1[i][1],
                                 acc2[i][2] - acc0[i][2] - acc1[i][2],
                                 acc2[i][3] - acc0[i][3] - acc1[i][3]);
        *(float4*)(g_T_re + tbase + (size_t)(f0 + i) * DD + n0) = wre;
        *(float4*)(g_T_im + tbase + (size_t)(f0 + i) * DD + n0) = wim;
    }
}

// ---------------- kernel 4: C[b] = T[b] @ A^H, Hermitian-half + mirror -------
__global__ __launch_bounds__(256) void gemm_stage2(float* __restrict__ out) {
    int bg = blockIdx.x;   // g tile (0..32)
    int bf = blockIdx.y;   // f tile (0..32)
    int b  = blockIdx.z;
    if (bg < bf) return;   // Hermitian: only upper tile pairs
    __shared__ __align__(16) float sA[3][BK][64];
    __shared__ __align__(16) float sB[3][BK][64];
    int tid = threadIdx.x;
    const size_t tbase = (size_t)b * FP * DD;

    float acc0[4][4] = {}, acc1[4][4] = {}, acc2[4][4] = {};

    const int am = tid >> 2;
    const int ak = (tid & 3) << 2;
    const size_t aoff = tbase + (size_t)(bf * 64 + am) * DD + ak;   // T rows (f)
    const size_t boff = (size_t)(bg * 64 + am) * DD + ak;           // A rows (g)
    const int tx = tid & 15, ty = tid >> 4;

    for (int k0 = 0; k0 < DD; k0 += BK) {
        float4 vr = *(const float4*)(g_T_re + aoff + k0);
        float4 vi = *(const float4*)(g_T_im + aoff + k0);
        sA[0][ak + 0][am] = vr.x; sA[1][ak + 0][am] = vi.x; sA[2][ak + 0][am] = vr.x + vi.x;
        sA[0][ak + 1][am] = vr.y; sA[1][ak + 1][am] = vi.y; sA[2][ak + 1][am] = vr.y + vi.y;
        sA[0][ak + 2][am] = vr.z; sA[1][ak + 2][am] = vi.z; sA[2][ak + 2][am] = vr.z + vi.z;
        sA[0][ak + 3][am] = vr.w; sA[1][ak + 3][am] = vi.w; sA[2][ak + 3][am] = vr.w + vi.w;
        // B side = conj(A[g]):  (re, -im, re-im)
        float4 wr = *(const float4*)(g_A_re + boff + k0);
        float4 wi = *(const float4*)(g_A_im + boff + k0);
        sB[0][ak + 0][am] = wr.x; sB[1][ak + 0][am] = -wi.x; sB[2][ak + 0][am] = wr.x - wi.x;
        sB[0][ak + 1][am] = wr.y; sB[1][ak + 1][am] = -wi.y; sB[2][ak + 1][am] = wr.y - wi.y;
        sB[0][ak + 2][am] = wr.z; sB[1][ak + 2][am] = -wi.z; sB[2][ak + 2][am] = wr.z - wi.z;
        sB[0][ak + 3][am] = wr.w; sB[1][ak + 3][am] = -wi.w; sB[2][ak + 3][am] = wr.w - wi.w;
        __syncthreads();
        mma_tile(sA, sB, ty, tx, acc0, acc1, acc2);
        __syncthreads();
    }

    float2* o = (float2*)out;
    int f0 = bf * 64 + ty * 4, g0 = bg * 64 + tx * 4;
#pragma unroll
    for (int i = 0; i < 4; ++i)
#pragma unroll
        for (int jx = 0; jx < 4; ++jx) {
            int f = f0 + i, g = g0 + jx;
            if (f < F_OUT && g < F_OUT && f <= g) {
                float re = acc0[i][jx] - acc1[i][jx];
                float im = acc2[i][jx] - acc0[i][jx] - acc1[i][jx];
                if (f == g) im = 0.f;   // reference cancels diag imag exactly
                o[((size_t)b * F_OUT + f) * F_OUT + g] = make_float2(re, im);
                if (f < g)
                    o[((size_t)b * F_OUT + g) * F_OUT + f] = make_float2(re, -im);
            }
        }
}

// ---------------- launch -----------------------------------------------------
extern "C" void kernel_launch(void* const* d_in, const int* in_sizes, int n_in,
                              void* d_out, int out_size) {
    const float* rho_re = (const float*)d_in[0];
    const float* rho_im = (const float*)d_in[1];
    const float* U_re   = (const float*)d_in[2];
    const float* U_im   = (const float*)d_in[3];

    build_amps<<<FP, 256>>>(U_re, U_im);
    hermitize<<<dim3(32, 32, NB), dim3(32, 32)>>>(rho_re, rho_im);
    gemm_stage1<<<dim3(16, 33, NB), 256>>>();
    gemm_stage2<<<dim3(33, 33, NB), 256>>>((float*)d_out);
}

// round 4
// speedup vs baseline: 2.0281x; 2.0281x over previous
#include <cuda_runtime.h>
#include <cuda_bf16.h>
#include <cstdint>

#define F_OUT 2080
#define FP2   2176                // 17*128, 34*64
#define DD    1024
#define NB    16
#define KEFF  6144                // 6 bf16 slots per original k
#define BK    64
#define NIT   96                  // KEFF/BK
#define BUFSZ 32768               // 16KB A + 8KB Bre + 8KB Bim
#define SMEM_BYTES 65536

typedef __nv_bfloat16 bf16;

__device__ bf16 g_Apk [(size_t)FP2 * KEFF];
__device__ bf16 g_A2re[(size_t)FP2 * KEFF];
__device__ bf16 g_A2im[(size_t)FP2 * KEFF];
__device__ bf16 g_Bre [(size_t)NB * DD * KEFF];
__device__ bf16 g_Bim [(size_t)NB * DD * KEFF];
__device__ bf16 g_Tpk [(size_t)NB * FP2 * KEFF];

// ---------------- helpers ----------------------------------------------------
__device__ __forceinline__ uint32_t s2u(const void* p) {
    uint32_t a; asm("{ .reg .u64 t; cvta.to.shared.u64 t, %1; cvt.u32.u64 %0, t; }"
                    : "=r"(a) : "l"(p)); return a;
}
__device__ __forceinline__ void cpa(uint32_t sa, const void* g) {
    asm volatile("cp.async.cg.shared.global [%0], [%1], 16;" :: "r"(sa), "l"(g));
}
#define CP_COMMIT() asm volatile("cp.async.commit_group;" ::: "memory")
#define CP_WAIT0()  asm volatile("cp.async.wait_group 0;" ::: "memory")

__device__ __forceinline__ void ldsm4(uint32_t (&r)[4], uint32_t a) {
    asm volatile("ldmatrix.sync.aligned.m8n8.x4.shared.b16 {%0,%1,%2,%3}, [%4];"
        : "=r"(r[0]), "=r"(r[1]), "=r"(r[2]), "=r"(r[3]) : "r"(a));
}
__device__ __forceinline__ void mma16816(float (&d)[4], const uint32_t (&a)[4],
                                         uint32_t b0, uint32_t b1) {
    asm volatile("mma.sync.aligned.m16n8k16.row.col.f32.bf16.bf16.f32 "
        "{%0,%1,%2,%3},{%4,%5,%6,%7},{%8,%9},{%0,%1,%2,%3};"
        : "+f"(d[0]), "+f"(d[1]), "+f"(d[2]), "+f"(d[3])
        : "r"(a[0]), "r"(a[1]), "r"(a[2]), "r"(a[3]), "r"(b0), "r"(b1));
}
__device__ __forceinline__ void splt(float x, float& h, float& l) {
    h = __bfloat162float(__float2bfloat16_rn(x)); l = x - h;
}
__device__ __forceinline__ uint32_t pk2(float a, float b) {
    unsigned short ua = __bfloat16_as_ushort(__float2bfloat16_rn(a));
    unsigned short ub = __bfloat16_as_ushort(__float2bfloat16_rn(b));
    return (uint32_t)ua | ((uint32_t)ub << 16);
}

// ---------------- pack A (stage1 A-plane + stage2 B-planes) ------------------
__global__ void pack_amps(const float* __restrict__ U_re, const float* __restrict__ U_im) {
    int f = blockIdx.x, t = threadIdx.x;
    if (f >= F_OUT) {
        uint4 z = make_uint4(0, 0, 0, 0);
        uint4* a = (uint4*)(g_Apk  + (size_t)f * KEFF);
        uint4* r = (uint4*)(g_A2re + (size_t)f * KEFF);
        uint4* m = (uint4*)(g_A2im + (size_t)f * KEFF);
        for (int i = t; i < KEFF / 8; i += 256) { a[i] = z; r[i] = z; m[i] = z; }
        return;
    }
    int j = 0, rem = f;
    while (rem >= 64 - j) { rem -= 64 - j; ++j; }
    int k = j + rem;
    __shared__ float su[4][64];
    if (t < 64) { su[0][t] = U_re[j*64+t]; su[1][t] = U_im[j*64+t];
                  su[2][t] = U_re[k*64+t]; su[3][t] = U_im[k*64+t]; }
    __syncthreads();
    float sc = (j == k) ? 0.7071067811865476f : 1.0f;
    for (int i = t; i < DD; i += 256) {
        int x = i >> 5, y = i & 31;
        float ar = su[0][x], ai = su[1][x], br = su[2][32+y], bi = su[3][32+y];
        float cr = su[2][x], ci = su[3][x], dr = su[0][32+y], di = su[1][32+y];
        float re = sc * (ar*br - ai*bi + cr*dr - ci*di);
        float im = sc * (ar*bi + ai*br + cr*di + ci*dr);
        float rh, rl, ih, il; splt(re, rh, rl); splt(im, ih, il);
        size_t e = (size_t)f * KEFF + 6 * i;
        uint32_t* pA = (uint32_t*)(g_Apk  + e);
        uint32_t* pR = (uint32_t*)(g_A2re + e);
        uint32_t* pI = (uint32_t*)(g_A2im + e);
        pA[0]=pk2(rh,rl);   pA[1]=pk2(rh,ih);  pA[2]=pk2(il,ih);
        pR[0]=pk2(rh,rh);   pR[1]=pk2(rl,ih);  pR[2]=pk2(ih,il);
        pI[0]=pk2(-ih,-ih); pI[1]=pk2(-il,rh); pI[2]=pk2(rh,rl);
    }
}

// ---------------- pack B (stage1 B-planes from rho upper triangle) -----------
__global__ void pack_B(const float* __restrict__ rr, const float* __restrict__ ri) {
    int n = blockIdx.x, b = blockIdx.y, t = threadIdx.x;
    const size_t rb = (size_t)b * DD * DD;
    for (int k = t; k < DD; k += 256) {
        float Br, Bi;
        if (k < n)      { Br = rr[rb + (size_t)k*DD + n]; Bi = ri[rb + (size_t)k*DD + n]; }
        else if (k > n) { Br = rr[rb + (size_t)n*DD + k]; Bi = -ri[rb + (size_t)n*DD + k]; }
        else            { Br = rr[rb + (size_t)n*DD + n]; Bi = 0.f; }
        float rh, rl, ih, il; splt(Br, rh, rl); splt(Bi, ih, il);
        size_t e = ((size_t)b*DD + n) * KEFF + 6*k;
        uint32_t* pR = (uint32_t*)(g_Bre + e);
        uint32_t* pI = (uint32_t*)(g_Bim + e);
        pR[0]=pk2(rh,rh); pR[1]=pk2(rl,-ih); pR[2]=pk2(-ih,-il);
        pI[0]=pk2(ih,ih); pI[1]=pk2(il,rh);  pI[2]=pk2(rh,rl);
    }
}

// ---------------- warp-MMA GEMM (both stages) --------------------------------
template <int STAGE>
__global__ void __launch_bounds__(256, 2) gemm_mma(float* __restrict__ out) {
    const int tid = threadIdx.x, lane = tid & 31, wid = tid >> 5;
    const int bx = blockIdx.x, by = blockIdx.y, bz = blockIdx.z;
    if (STAGE == 2 && 64 * (bx + 1) <= 128 * by) return;   // tile fully below diag
    extern __shared__ __align__(128) char smem[];
    const uint32_t sb = s2u(smem);

    const bf16 *Ag, *Brg, *Big;
    if (STAGE == 1) {
        Ag  = g_Apk + (size_t)(by * 128) * KEFF;
        Brg = g_Bre + ((size_t)bz * DD + bx * 64) * KEFF;
        Big = g_Bim + ((size_t)bz * DD + bx * 64) * KEFF;
    } else {
        Ag  = g_Tpk + ((size_t)bz * FP2 + by * 128) * KEFF;
        Brg = g_A2re + (size_t)(bx * 64) * KEFF;
        Big = g_A2im + (size_t)(bx * 64) * KEFF;
    }
    const int plane = wid & 1, nh = (wid >> 1) & 1, mh = wid >> 2;

    float acc[4][4][4];
#pragma unroll
    for (int a = 0; a < 4; ++a)
#pragma unroll
        for (int b2 = 0; b2 < 4; ++b2)
#pragma unroll
            for (int c2 = 0; c2 < 4; ++c2) acc[a][b2][c2] = 0.f;

    const int arow = tid >> 1, ahalf = tid & 1;
    const int brow = tid >> 2, bq = tid & 3;

    // ---- prologue load chunk 0
    {
        uint32_t bufb = sb;
        const bf16* asrc = Ag + (size_t)arow * KEFF + ahalf * 32;
#pragma unroll
        for (int i = 0; i < 4; ++i) {
            int ch = ahalf * 4 + i;
            cpa(bufb + arow * 128 + ((ch ^ (arow & 7)) << 4), asrc + i * 8);
        }
        const bf16* rsrc = Brg + (size_t)brow * KEFF + bq * 16;
        const bf16* isrc = Big + (size_t)brow * KEFF + bq * 16;
#pragma unroll
        for (int i = 0; i < 2; ++i) {
            int ch = bq * 2 + i;
            cpa(bufb + 16384 + brow * 128 + ((ch ^ (brow & 7)) << 4), rsrc + i * 8);
            cpa(bufb + 24576 + brow * 128 + ((ch ^ (brow & 7)) << 4), isrc + i * 8);
        }
        CP_COMMIT();
    }

    for (int c = 0; c < NIT; ++c) {
        CP_WAIT0();
        __syncthreads();
        if (c + 1 < NIT) {
            uint32_t bufb = sb + ((c + 1) & 1) * BUFSZ;
            const bf16* asrc = Ag + (size_t)arow * KEFF + (c + 1) * BK + ahalf * 32;
#pragma unroll
            for (int i = 0; i < 4; ++i) {
                int ch = ahalf * 4 + i;
                cpa(bufb + arow * 128 + ((ch ^ (arow & 7)) << 4), asrc + i * 8);
            }
            const bf16* rsrc = Brg + (size_t)brow * KEFF + (c + 1) * BK + bq * 16;
            const bf16* isrc = Big + (size_t)brow * KEFF + (c + 1) * BK + bq * 16;
#pragma unroll
            for (int i = 0; i < 2; ++i) {
                int ch = bq * 2 + i;
                cpa(bufb + 16384 + brow * 128 + ((ch ^ (brow & 7)) << 4), rsrc + i * 8);
                cpa(bufb + 24576 + brow * 128 + ((ch ^ (brow & 7)) << 4), isrc + i * 8);
            }
            CP_COMMIT();
        }
        // ---- compute on buffer c&1
        uint32_t bufb = sb + (c & 1) * BUFSZ;
        const uint32_t sA = bufb;
        const uint32_t sB = bufb + 16384 + plane * 8192;
#pragma unroll
        for (int ks = 0; ks < 4; ++ks) {
            uint32_t af[4][4];
#pragma unroll
            for (int mi = 0; mi < 4; ++mi) {
                int m = mh * 64 + mi * 16 + (lane & 15);
                int ch = ks * 2 + (lane >> 4);
                ldsm4(af[mi], sA + m * 128 + ((ch ^ (m & 7)) << 4));
            }
            uint32_t bfr[2][4];
#pragma unroll
            for (int nj = 0; nj < 2; ++nj) {
                int n = nh * 32 + nj * 16 + (lane & 7) + ((lane >> 4) << 3);
                int ch = ks * 2 + ((lane >> 3) & 1);
                ldsm4(bfr[nj], sB + n * 128 + ((ch ^ (n & 7)) << 4));
            }
#pragma unroll
            for (int mi = 0; mi < 4; ++mi)
#pragma unroll
                for (int ni = 0; ni < 4; ++ni)
                    mma16816(acc[mi][ni], af[mi],
                             bfr[ni >> 1][(ni & 1) * 2], bfr[ni >> 1][(ni & 1) * 2 + 1]);
        }
    }

    // ---- epilogue: stage accums (re plane @0, im plane @32KB) ---------------
    __syncthreads();
    float* stR = (float*)smem;
    float* stI = (float*)(smem + 32768);
    float* st = plane ? stI : stR;
#pragma unroll
    for (int mi = 0; mi < 4; ++mi)
#pragma unroll
        for (int ni = 0; ni < 4; ++ni) {
            int r0 = mh * 64 + mi * 16 + (lane >> 2);
            int col = nh * 32 + ni * 8 + (lane & 3) * 2;
            *(float2*)&st[r0 * 64 + col]       = make_float2(acc[mi][ni][0], acc[mi][ni][1]);
            *(float2*)&st[(r0 + 8) * 64 + col] = make_float2(acc[mi][ni][2], acc[mi][ni][3]);
        }
    __syncthreads();

    const int row = tid >> 1;
    const int c0 = (tid & 1) * 32;
    if (STAGE == 1) {
        int f = by * 128 + row;
        char* Trow = (char*)(g_Tpk + ((size_t)bz * FP2 + f) * KEFF);
#pragma unroll 4
        for (int j2 = 0; j2 < 32; ++j2) {
            float re = stR[row * 64 + c0 + j2];
            float im = stI[row * 64 + c0 + j2];
            float rh, rl, ih, il; splt(re, rh, rl); splt(im, ih, il);
            int n = bx * 64 + c0 + j2;
            uint32_t* p = (uint32_t*)(Trow + 12 * n);
            p[0] = pk2(rh, rl); p[1] = pk2(rh, ih); p[2] = pk2(il, ih);
        }
    } else {
        int f = by * 128 + row;
        if (f < F_OUT) {
            float2* o = (float2*)out + (size_t)bz * F_OUT * F_OUT;
#pragma unroll 4
            for (int j2 = 0; j2 < 32; ++j2) {
                int g = bx * 64 + c0 + j2;
                if (g < F_OUT && f <= g) {
                    float re = stR[row * 64 + c0 + j2];
                    float im = stI[row * 64 + c0 + j2];
                    if (f == g) im = 0.f;
                    o[(size_t)f * F_OUT + g] = make_float2(re, im);
                    if (f < g) o[(size_t)g * F_OUT + f] = make_float2(re, -im);
                }
            }
        }
    }
}

// ---------------- launch -----------------------------------------------------
extern "C" void kernel_launch(void* const* d_in, const int* in_sizes, int n_in,
                              void* d_out, int out_size) {
    const float* rho_re = (const float*)d_in[0];
    const float* rho_im = (const float*)d_in[1];
    const float* U_re   = (const float*)d_in[2];
    const float* U_im   = (const float*)d_in[3];

    cudaFuncSetAttribute(gemm_mma<1>, cudaFuncAttributeMaxDynamicSharedMemorySize, SMEM_BYTES);
    cudaFuncSetAttribute(gemm_mma<2>, cudaFuncAttributeMaxDynamicSharedMemorySize, SMEM_BYTES);

    pack_amps<<<FP2, 256>>>(U_re, U_im);
    pack_B<<<dim3(DD, NB), 256>>>(rho_re, rho_im);
    gemm_mma<1><<<dim3(16, 17, NB), 256, SMEM_BYTES>>>(nullptr);
    gemm_mma<2><<<dim3(34, 17, NB), 256, SMEM_BYTES>>>((float*)d_out);
}